// round 17
// baseline (speedup 1.0000x reference)
#include <cuda_runtime.h>
#include <cuda_fp16.h>
#include <math.h>
#include <stdint.h>

// Problem constants
#define B_   4
#define T_   2048
#define S_   2048
#define DQ_  512
#define DKV_ 1024
#define H_   8
#define HD_  64
#define TR   16      // t-rows per fused-attention block
#define ESTR 2056    // E row stride in halves (2048 + 8 pad; 1028 words ≡ 4 mod 32)

// Scratch buffers (allocation-free: __device__ globals)
__device__ __half g_qin[B_ * T_ * DQ_];
__device__ __half g_kin[B_ * S_ * DKV_];
__device__ __half g_vin[B_ * S_ * DKV_];
__device__ __half g_Wqt[DQ_ * DQ_];
__device__ __half g_Wkt[DQ_ * DKV_];
__device__ __half g_Wvt[DQ_ * DKV_];
__device__ __half g_Wot[DQ_ * DQ_];
__device__ __half g_Qh[B_ * T_ * DQ_];
__device__ __half g_Kh[B_ * S_ * DQ_];
__device__ __half g_Vt[B_ * H_ * HD_ * (size_t)S_];
__device__ __half g_ctxh[B_ * T_ * DQ_];

// ---------------------------------------------------------------------------
// Helpers
// ---------------------------------------------------------------------------
__device__ __forceinline__ void mma_f16(float d[4],
                                        uint32_t a0, uint32_t a1, uint32_t a2, uint32_t a3,
                                        uint32_t b0, uint32_t b1) {
    asm volatile(
        "mma.sync.aligned.m16n8k16.row.col.f32.f16.f16.f32 "
        "{%0,%1,%2,%3}, {%4,%5,%6,%7}, {%8,%9}, {%0,%1,%2,%3};\n"
        : "+f"(d[0]), "+f"(d[1]), "+f"(d[2]), "+f"(d[3])
        : "r"(a0), "r"(a1), "r"(a2), "r"(a3), "r"(b0), "r"(b1));
}

__device__ __forceinline__ void cp_async16(uint32_t s, const void* g) {
    asm volatile("cp.async.cg.shared.global [%0], [%1], 16;\n" :: "r"(s), "l"(g));
}
__device__ __forceinline__ void cp_commit() { asm volatile("cp.async.commit_group;\n" ::: "memory"); }
__device__ __forceinline__ void cp_wait0()  { asm volatile("cp.async.wait_group 0;\n" ::: "memory"); }

// ---------------------------------------------------------------------------
// fp32 -> half (vectorized)
// ---------------------------------------------------------------------------
__global__ __launch_bounds__(256) void cvt_f2h(
    const float* __restrict__ src, __half* __restrict__ dst, int n)
{
    int i = (blockIdx.x * 256 + threadIdx.x) * 4;
    if (i < n) {
        float4 v = *(const float4*)(src + i);
        __half2* d = (__half2*)(dst + i);
        d[0] = __floats2half2_rn(v.x, v.y);
        d[1] = __floats2half2_rn(v.z, v.w);
    }
}

// ---------------------------------------------------------------------------
// W [K][N] fp32 -> Wt [N][K] half (smem tile transpose)
// ---------------------------------------------------------------------------
__global__ __launch_bounds__(256) void cvt_tr(
    const float* __restrict__ W, __half* __restrict__ Wt, int K, int N)
{
    __shared__ float tile[32][33];
    int k0 = blockIdx.y * 32, n0 = blockIdx.x * 32;
    int tx = threadIdx.x & 31, ty = threadIdx.x >> 5;
    #pragma unroll
    for (int j = ty; j < 32; j += 8)
        tile[j][tx] = W[(size_t)(k0 + j) * N + n0 + tx];
    __syncthreads();
    #pragma unroll
    for (int j = ty; j < 32; j += 8)
        Wt[(size_t)(n0 + j) * K + k0 + tx] = __float2half(tile[tx][j]);
}

// ---------------------------------------------------------------------------
// All-half GEMM (proven R16): C = A @ Wt^T + bias
// MODE 0: fp32 out. MODE 1: half out. MODE 2: half out, Vt layout.
// ---------------------------------------------------------------------------
template <int MODE>
__global__ __launch_bounds__(128, 4) void gemm_h(
    const __half* __restrict__ A, const __half* __restrict__ Wt,
    const float* __restrict__ bias, void* __restrict__ Cout,
    int M, int N, int K)
{
    extern __shared__ __half hsm[];
    __half* As = hsm;                 // [2][128][72]
    __half* Bs = hsm + 2 * 128 * 72;  // [2][64][72]
    const uint32_t abase = (uint32_t)__cvta_generic_to_shared(As);
    const uint32_t bbase = (uint32_t)__cvta_generic_to_shared(Bs);

    const int tid = threadIdx.x;
    const int wid = tid >> 5, lane = tid & 31;
    const int g = lane >> 2, tg = lane & 3;
    const int bm = blockIdx.y * 128, bn = blockIdx.x * 64;
    const int wm = (wid >> 1) * 64, wn = (wid & 1) * 32;

    float acc[4][4][4];
    #pragma unroll
    for (int mt = 0; mt < 4; mt++)
        #pragma unroll
        for (int nt = 0; nt < 4; nt++)
            #pragma unroll
            for (int r = 0; r < 4; r++) acc[mt][nt][r] = 0.f;

    auto load_stage = [&](int buf, int k0) {
        uint32_t ab = abase + (uint32_t)buf * 128 * 72 * 2;
        #pragma unroll
        for (int i = tid; i < 128 * 8; i += 128) {
            int r = i >> 3, seg = i & 7;
            cp_async16(ab + (r * 72 + seg * 8) * 2,
                       A + (size_t)(bm + r) * K + k0 + seg * 8);
        }
        uint32_t bb = bbase + (uint32_t)buf * 64 * 72 * 2;
        #pragma unroll
        for (int i = tid; i < 64 * 8; i += 128) {
            int r = i >> 3, seg = i & 7;
            cp_async16(bb + (r * 72 + seg * 8) * 2,
                       Wt + (size_t)(bn + r) * K + k0 + seg * 8);
        }
        cp_commit();
    };

    load_stage(0, 0);
    int buf = 0;
    for (int k0 = 0; k0 < K; k0 += 64, buf ^= 1) {
        cp_wait0();
        __syncthreads();
        if (k0 + 64 < K) load_stage(buf ^ 1, k0 + 64);

        const __half* Ab = As + buf * 128 * 72;
        const __half* Bb = Bs + buf * 64 * 72;
        #pragma unroll
        for (int ks = 0; ks < 4; ks++) {
            const int kk = ks * 16;
            uint32_t a[4][4], bf[4][2];
            #pragma unroll
            for (int mt = 0; mt < 4; mt++) {
                int mr = wm + mt * 16;
                a[mt][0] = *(const uint32_t*)(Ab + (mr + g) * 72 + kk + 2 * tg);
                a[mt][1] = *(const uint32_t*)(Ab + (mr + g + 8) * 72 + kk + 2 * tg);
                a[mt][2] = *(const uint32_t*)(Ab + (mr + g) * 72 + kk + 8 + 2 * tg);
                a[mt][3] = *(const uint32_t*)(Ab + (mr + g + 8) * 72 + kk + 8 + 2 * tg);
            }
            #pragma unroll
            for (int nt = 0; nt < 4; nt++) {
                int nc = wn + nt * 8 + g;
                bf[nt][0] = *(const uint32_t*)(Bb + nc * 72 + kk + 2 * tg);
                bf[nt][1] = *(const uint32_t*)(Bb + nc * 72 + kk + 8 + 2 * tg);
            }
            #pragma unroll
            for (int mt = 0; mt < 4; mt++)
                #pragma unroll
                for (int nt = 0; nt < 4; nt++)
                    mma_f16(acc[mt][nt], a[mt][0], a[mt][1], a[mt][2], a[mt][3],
                            bf[nt][0], bf[nt][1]);
        }
    }

    #pragma unroll
    for (int mt = 0; mt < 4; mt++) {
        #pragma unroll
        for (int nt = 0; nt < 4; nt++) {
            int n0 = bn + wn + nt * 8 + tg * 2;
            float b0v = bias[n0], b1v = bias[n0 + 1];
            int r0 = bm + wm + mt * 16 + g;
            float v00 = acc[mt][nt][0] + b0v, v01 = acc[mt][nt][1] + b1v;
            float v10 = acc[mt][nt][2] + b0v, v11 = acc[mt][nt][3] + b1v;
            if (MODE == 0) {
                float* C = (float*)Cout;
                C[(size_t)r0 * N + n0]           = v00;
                C[(size_t)r0 * N + n0 + 1]       = v01;
                C[(size_t)(r0 + 8) * N + n0]     = v10;
                C[(size_t)(r0 + 8) * N + n0 + 1] = v11;
            } else if (MODE == 1) {
                __half* C = (__half*)Cout;
                C[(size_t)r0 * N + n0]           = __float2half(v00);
                C[(size_t)r0 * N + n0 + 1]       = __float2half(v01);
                C[(size_t)(r0 + 8) * N + n0]     = __float2half(v10);
                C[(size_t)(r0 + 8) * N + n0 + 1] = __float2half(v11);
            } else {
                __half* C = (__half*)Cout;
                int h0 = n0 >> 6, d0 = n0 & 63;
                int b0i = r0 >> 11, t0i = r0 & 2047;
                size_t base0 = ((size_t)(b0i * 8 + h0) * 64 + d0) * 2048;
                C[base0 + t0i]            = __float2half(v00);
                C[base0 + 2048 + t0i]     = __float2half(v01);
                C[base0 + t0i + 8]        = __float2half(v10);
                C[base0 + 2048 + t0i + 8] = __float2half(v11);
            }
        }
    }
}

// ---------------------------------------------------------------------------
// FUSED attention: per block = 16 t-rows x one (b,h).
// Phase 1: scores = Q.K^T/8 + mask (kpm -> -inf) -> E = exp in smem (half)
//          + per-row sums (register-accumulated).
// Phase 2a: attn = E * inv  (single coalesced DRAM pass over attn tensor).
// Phase 2b: ctx = (E @ V) * inv  -> ctxh.
// 8 warps: warp w owns n-cols w*8..w*8+7 (s in phase 1, d in phase 2b).
// ---------------------------------------------------------------------------
__global__ __launch_bounds__(256, 2) void fused_attn(
    const __half* __restrict__ Qh, const __half* __restrict__ Kh,
    const __half* __restrict__ Vt,
    const float* __restrict__ attn_mask, const int* __restrict__ kpm,
    float* __restrict__ attn, __half* __restrict__ ctxh)
{
    extern __shared__ __half sm[];
    __half* E  = sm;                        // [TR][ESTR]
    __half* Kb = sm + TR * ESTR;            // [2][64][72]
    __half* Vb = Kb + 2 * 64 * 72;          // [2][64][72]
    __half* Qs = Vb + 2 * 64 * 72;          // [TR][72]
    float*  Ps = (float*)(Qs + TR * 72);    // [16][32]
    float*  inv_s = Ps + 16 * 32;           // [16]
    const uint32_t kbase = (uint32_t)__cvta_generic_to_shared(Kb);
    const uint32_t vbase = (uint32_t)__cvta_generic_to_shared(Vb);
    const uint32_t qbase = (uint32_t)__cvta_generic_to_shared(Qs);

    const int tid = threadIdx.x;
    const int wid = tid >> 5, lane = tid & 31;
    const int g = lane >> 2, tg = lane & 3;
    const int bh = blockIdx.y;
    const int b = bh >> 3, h = bh & 7;
    const int t0 = blockIdx.x * TR;

    auto load_k = [&](int buf, int s0) {
        uint32_t kb = kbase + (uint32_t)buf * 64 * 72 * 2;
        #pragma unroll
        for (int i = tid; i < 64 * 8; i += 256) {
            int r = i >> 3, seg = i & 7;
            cp_async16(kb + (r * 72 + seg * 8) * 2,
                       Kh + (size_t)(b * S_ + s0 + r) * DQ_ + h * HD_ + seg * 8);
        }
        cp_commit();
    };
    auto load_v = [&](int buf, int k0) {
        uint32_t vb = vbase + (uint32_t)buf * 64 * 72 * 2;
        #pragma unroll
        for (int i = tid; i < 64 * 8; i += 256) {
            int r = i >> 3, seg = i & 7;
            cp_async16(vb + (r * 72 + seg * 8) * 2,
                       Vt + ((size_t)bh * HD_ + r) * S_ + k0 + seg * 8);
        }
        cp_commit();
    };

    // Q tile (16 rows x 128B) + first K chunk
    if (tid < TR * 8) {
        int r = tid >> 3, seg = tid & 7;
        cp_async16(qbase + (r * 72 + seg * 8) * 2,
                   Qh + (size_t)(b * T_ + t0 + r) * DQ_ + h * HD_ + seg * 8);
    }
    load_k(0, 0);

    uint32_t aq[4][4];
    float sum_lo = 0.f, sum_hi = 0.f;

    int buf = 0;
    for (int s0 = 0; s0 < S_; s0 += 64, buf ^= 1) {
        cp_wait0();
        __syncthreads();
        if (s0 == 0) {
            // preload Q fragments (fixed for whole phase)
            #pragma unroll
            for (int ks = 0; ks < 4; ks++) {
                const int kk = ks * 16;
                aq[ks][0] = *(const uint32_t*)(Qs + g * 72 + kk + 2 * tg);
                aq[ks][1] = *(const uint32_t*)(Qs + (g + 8) * 72 + kk + 2 * tg);
                aq[ks][2] = *(const uint32_t*)(Qs + g * 72 + kk + 8 + 2 * tg);
                aq[ks][3] = *(const uint32_t*)(Qs + (g + 8) * 72 + kk + 8 + 2 * tg);
            }
        }
        if (s0 + 64 < S_) load_k(buf ^ 1, s0 + 64);

        const __half* Kc = Kb + buf * 64 * 72;
        float acc[4] = {0.f, 0.f, 0.f, 0.f};
        const int nc = wid * 8 + g;
        #pragma unroll
        for (int ks = 0; ks < 4; ks++) {
            const int kk = ks * 16;
            uint32_t b0 = *(const uint32_t*)(Kc + nc * 72 + kk + 2 * tg);
            uint32_t b1 = *(const uint32_t*)(Kc + nc * 72 + kk + 8 + 2 * tg);
            mma_f16(acc, aq[ks][0], aq[ks][1], aq[ks][2], aq[ks][3], b0, b1);
        }

        // epilogue: +mask, kpm, exp -> E; accumulate row sums
        const int s = s0 + wid * 8 + 2 * tg;
        int2 kp2 = *(const int2*)(kpm + b * S_ + s);
        float2 mlo = *(const float2*)(attn_mask + (size_t)(t0 + g) * S_ + s);
        float2 mhi = *(const float2*)(attn_mask + (size_t)(t0 + g + 8) * S_ + s);
        float e00 = (kp2.x == 0) ? 0.f : __expf(acc[0] * 0.125f + mlo.x);
        float e01 = (kp2.y == 0) ? 0.f : __expf(acc[1] * 0.125f + mlo.y);
        float e10 = (kp2.x == 0) ? 0.f : __expf(acc[2] * 0.125f + mhi.x);
        float e11 = (kp2.y == 0) ? 0.f : __expf(acc[3] * 0.125f + mhi.y);
        *(__half2*)(E + (size_t)g * ESTR + s)       = __floats2half2_rn(e00, e01);
        *(__half2*)(E + (size_t)(g + 8) * ESTR + s) = __floats2half2_rn(e10, e11);
        sum_lo += e00 + e01;
        sum_hi += e10 + e11;
    }

    // row sums -> inv
    Ps[g * 32 + wid * 4 + tg]       = sum_lo;
    Ps[(g + 8) * 32 + wid * 4 + tg] = sum_hi;
    __syncthreads();
    if (tid < 16) {
        float s = 0.f;
        #pragma unroll
        for (int j = 0; j < 8; j++) {
            float4 v = *(const float4*)(Ps + tid * 32 + j * 4);
            s += v.x + v.y + v.z + v.w;
        }
        inv_s[tid] = 1.0f / s;
    }
    __syncthreads();

    // Phase 2a: attn = E * inv  (coalesced float4)
    float* arow = attn + ((size_t)bh * T_ + t0) * S_;
    #pragma unroll 4
    for (int idx = tid; idx < TR * 512; idx += 256) {
        int r = idx >> 9, c4 = (idx & 511) * 4;
        __half2 h0 = *(const __half2*)(E + (size_t)r * ESTR + c4);
        __half2 h1 = *(const __half2*)(E + (size_t)r * ESTR + c4 + 2);
        float iv = inv_s[r];
        float4 p;
        p.x = __low2float(h0) * iv;  p.y = __high2float(h0) * iv;
        p.z = __low2float(h1) * iv;  p.w = __high2float(h1) * iv;
        *(float4*)(arow + (size_t)r * S_ + c4) = p;
    }

    // Phase 2b: ctx = (E @ V) * inv
    load_v(0, 0);
    float accv[4] = {0.f, 0.f, 0.f, 0.f};
    buf = 0;
    for (int k0 = 0; k0 < S_; k0 += 64, buf ^= 1) {
        cp_wait0();
        __syncthreads();
        if (k0 + 64 < S_) load_v(buf ^ 1, k0 + 64);

        const __half* Vc = Vb + buf * 64 * 72;
        const int nc = wid * 8 + g;
        #pragma unroll
        for (int ks = 0; ks < 4; ks++) {
            const int kk = k0 + ks * 16;
            uint32_t a0 = *(const uint32_t*)(E + (size_t)g * ESTR + kk + 2 * tg);
            uint32_t a1 = *(const uint32_t*)(E + (size_t)(g + 8) * ESTR + kk + 2 * tg);
            uint32_t a2 = *(const uint32_t*)(E + (size_t)g * ESTR + kk + 8 + 2 * tg);
            uint32_t a3 = *(const uint32_t*)(E + (size_t)(g + 8) * ESTR + kk + 8 + 2 * tg);
            uint32_t b0 = *(const uint32_t*)(Vc + nc * 72 + (ks * 16) + 2 * tg);
            uint32_t b1 = *(const uint32_t*)(Vc + nc * 72 + (ks * 16) + 8 + 2 * tg);
            mma_f16(accv, a0, a1, a2, a3, b0, b1);
        }
    }

    const int d0 = wid * 8 + 2 * tg;
    float ilo = inv_s[g], ihi = inv_s[g + 8];
    ctxh[(size_t)(b * T_ + t0 + g) * DQ_ + h * HD_ + d0]         = __float2half(accv[0] * ilo);
    ctxh[(size_t)(b * T_ + t0 + g) * DQ_ + h * HD_ + d0 + 1]     = __float2half(accv[1] * ilo);
    ctxh[(size_t)(b * T_ + t0 + g + 8) * DQ_ + h * HD_ + d0]     = __float2half(accv[2] * ihi);
    ctxh[(size_t)(b * T_ + t0 + g + 8) * DQ_ + h * HD_ + d0 + 1] = __float2half(accv[3] * ihi);
}

// ---------------------------------------------------------------------------
// Launch (single stream)
// ---------------------------------------------------------------------------
extern "C" void kernel_launch(void* const* d_in, const int* in_sizes, int n_in,
                              void* d_out, int out_size)
{
    const float* query     = (const float*)d_in[0];
    const float* key       = (const float*)d_in[1];
    const float* value     = (const float*)d_in[2];
    const int*   kpm       = (const int*)  d_in[3];
    const float* attn_mask = (const float*)d_in[4];
    const float* Wq = (const float*)d_in[5];
    const float* bq = (const float*)d_in[6];
    const float* Wk = (const float*)d_in[7];
    const float* bk = (const float*)d_in[8];
    const float* Wv = (const float*)d_in[9];
    const float* bv = (const float*)d_in[10];
    const float* Wo = (const float*)d_in[11];
    const float* bo = (const float*)d_in[12];

    float* out  = (float*)d_out;                        // [B,T,DQ]
    float* attn = out + (size_t)B_ * T_ * DQ_;          // [B,H,T,S]

    __half *qin, *kin, *vin, *Wqt, *Wkt, *Wvt, *Wot, *Qh, *Kh, *Vt, *ctxh;
    cudaGetSymbolAddress((void**)&qin, g_qin);
    cudaGetSymbolAddress((void**)&kin, g_kin);
    cudaGetSymbolAddress((void**)&vin, g_vin);
    cudaGetSymbolAddress((void**)&Wqt, g_Wqt);
    cudaGetSymbolAddress((void**)&Wkt, g_Wkt);
    cudaGetSymbolAddress((void**)&Wvt, g_Wvt);
    cudaGetSymbolAddress((void**)&Wot, g_Wot);
    cudaGetSymbolAddress((void**)&Qh, g_Qh);
    cudaGetSymbolAddress((void**)&Kh, g_Kh);
    cudaGetSymbolAddress((void**)&Vt, g_Vt);
    cudaGetSymbolAddress((void**)&ctxh, g_ctxh);

    const int GEMMH_SMEM = (2 * 128 * 72 + 2 * 64 * 72) * 2;   // 55296
    const int FUSED_SMEM = (TR * ESTR + 2 * 64 * 72 + 2 * 64 * 72 + TR * 72) * 2
                         + (16 * 32 + 16) * 4;                  // 107072

    static int attr_done = 0;
    if (!attr_done) {
        cudaFuncSetAttribute(gemm_h<0>,  cudaFuncAttributeMaxDynamicSharedMemorySize, GEMMH_SMEM);
        cudaFuncSetAttribute(gemm_h<1>,  cudaFuncAttributeMaxDynamicSharedMemorySize, GEMMH_SMEM);
        cudaFuncSetAttribute(gemm_h<2>,  cudaFuncAttributeMaxDynamicSharedMemorySize, GEMMH_SMEM);
        cudaFuncSetAttribute(fused_attn, cudaFuncAttributeMaxDynamicSharedMemorySize, FUSED_SMEM);
        attr_done = 1;
    }

    const int M = B_ * T_;   // 8192

    // Convert inputs and weights to half (weights transposed)
    cvt_f2h<<<(M * DQ_ / 4 + 255) / 256, 256>>>(query, qin, M * DQ_);
    cvt_f2h<<<(M * DKV_ / 4 + 255) / 256, 256>>>(key,   kin, M * DKV_);
    cvt_f2h<<<(M * DKV_ / 4 + 255) / 256, 256>>>(value, vin, M * DKV_);
    cvt_tr<<<dim3(DQ_ / 32, DQ_ / 32),  256>>>(Wq, Wqt, DQ_,  DQ_);
    cvt_tr<<<dim3(DQ_ / 32, DKV_ / 32), 256>>>(Wk, Wkt, DKV_, DQ_);
    cvt_tr<<<dim3(DQ_ / 32, DKV_ / 32), 256>>>(Wv, Wvt, DKV_, DQ_);
    cvt_tr<<<dim3(DQ_ / 32, DQ_ / 32),  256>>>(Wo, Wot, DQ_,  DQ_);

    // Projections (all-half fp16 mma)
    gemm_h<1><<<dim3(DQ_ / 64, M / 128), 128, GEMMH_SMEM>>>(qin, Wqt, bq, Qh, M, DQ_, DQ_);
    gemm_h<1><<<dim3(DQ_ / 64, M / 128), 128, GEMMH_SMEM>>>(kin, Wkt, bk, Kh, M, DQ_, DKV_);
    gemm_h<2><<<dim3(DQ_ / 64, M / 128), 128, GEMMH_SMEM>>>(vin, Wvt, bv, Vt, M, DQ_, DKV_);

    // Fused scores + softmax + AV: writes attn (once) and ctxh
    fused_attn<<<dim3(T_ / TR, B_ * H_), 256, FUSED_SMEM>>>(
        Qh, Kh, Vt, attn_mask, kpm, attn, ctxh);

    // Output projection (fp32 out)
    gemm_h<0><<<dim3(DQ_ / 64, M / 128), 128, GEMMH_SMEM>>>(ctxh, Wot, bo, out, M, DQ_, DQ_);
}